// round 13
// baseline (speedup 1.0000x reference)
#include <cuda_runtime.h>
#include <cuda_bf16.h>
#include <cuda_fp16.h>
#include <cstdint>

// B=4096, D=128. out[4096][16384] fp32.
// part1 (cols 0..8191)  = softmax([a@b.T , a@a.T - diag*INF])
// part2 (cols 8192..)   = softmax([b@a.T , b@b.T - diag*INF])
// GEMM: split-bf16 (hi+lo, 3 products) on mma.sync.m16n8k16, symmetry-halved
// (2080 tiles), fp16 stage for unnormalized exp.
// This round: persistent mega-kernel. 296 resident CTAs pull from a
// dependency-ordered queue of 2080 GEMM jobs + 2048 scale chunks; scale's
// DRAM traffic overlaps the tensor-bound GEMM via per-row-block counters.

#define NROWS 4096
#define DDIM  128
#define OCOLS 16384
#define LAG   6
#define QTOT  4128

__device__ float g_sums[2 * NROWS];
__device__ __align__(256) __nv_bfloat16 g_ah[NROWS * DDIM];
__device__ __align__(256) __nv_bfloat16 g_al[NROWS * DDIM];
__device__ __align__(256) __nv_bfloat16 g_bh[NROWS * DDIM];
__device__ __align__(256) __nv_bfloat16 g_bl[NROWS * DDIM];
__device__ __align__(256) __half g_stage[(size_t)NROWS * OCOLS];   // 128 MB fp16 exp stage
__device__ uint32_t g_queue[QTOT];
__device__ unsigned int g_done[64];     // [0..31] part1 blocks, [32..63] part2
__device__ unsigned int g_qhead;

// ---------------- normalize + bf16 hi/lo split + zero sums ----------------
__global__ void norm_kernel(const float* __restrict__ z1,
                            const float* __restrict__ z2) {
    int row = blockIdx.x;           // 0..8191
    int tid = threadIdx.x;          // 0..127
    const float* src; __nv_bfloat16 *dh, *dl; int r;
    if (row < NROWS) { src = z1; dh = g_ah; dl = g_al; r = row; }
    else             { src = z2; dh = g_bh; dl = g_bl; r = row - NROWS; }
    float v = src[r * DDIM + tid];
    float s = v * v;
    #pragma unroll
    for (int o = 16; o; o >>= 1) s += __shfl_xor_sync(0xffffffffu, s, o);
    __shared__ float ws[4];
    if ((tid & 31) == 0) ws[tid >> 5] = s;
    __syncthreads();
    float tot = ws[0] + ws[1] + ws[2] + ws[3];
    float vn = v * rsqrtf(fmaxf(tot, 1e-12f));
    __nv_bfloat16 h = __float2bfloat16(vn);
    float hr = __bfloat162float(h);
    __nv_bfloat16 l = __float2bfloat16(vn - hr);
    dh[r * DDIM + tid] = h;
    dl[r * DDIM + tid] = l;
    if (tid == 0) g_sums[row] = 0.0f;
}

// ---------------- queue layout ----------------
// Phase1: groups g=0..31: ab(g,0..31) then aa(g,g..31)  [64-g jobs]
//   S1_i (32 chunks) inserted after G1_{i+LAG}; S1_26..31 ride in phase2.
// Phase2: groups g=0..31: bb(g,g..31) [32-g jobs]
//   g<LAG: S1_{26+g} after G2_g;  g>=LAG: S2_{g-LAG} after G2_g; S2_26..31 at end.
__host__ __device__ __forceinline__ int p1_gstart(int g) {
    return 64 * g - (g * (g - 1)) / 2 + 32 * ((g > LAG) ? (g - LAG) : 0);
}
__host__ __device__ __forceinline__ int p2_gstart(int g) {
    int mn = (g < LAG) ? g : LAG;
    int mx = (g > LAG) ? (g - LAG) : 0;
    return 2384 + 32 * g - (g * (g - 1)) / 2 + 32 * mn + 32 * mx;
}

__global__ void init_kernel() {
    int tid = threadIdx.x;
    if (tid == 0) g_qhead = 0;
    if (tid < 64) g_done[tid] = 0;
    for (int g = 0; g < 32; g++) {
        int b1 = p1_gstart(g);
        for (int j = tid; j < 64 - g; j += 256)
            g_queue[b1 + j] = (j < 32) ? ((0u << 12) | (g << 6) | j)
                                       : ((1u << 12) | (g << 6) | (g + j - 32));
        int b2 = p2_gstart(g);
        for (int j = tid; j < 32 - g; j += 256)
            g_queue[b2 + j] = (2u << 12) | (g << 6) | (g + j);
    }
    for (int i = 0; i < 32; i++) {
        int sb1 = (i <= 31 - LAG) ? p1_gstart(i + LAG) + (64 - (i + LAG))
                                  : p2_gstart(i - 26) + (32 - (i - 26));
        for (int j = tid; j < 32; j += 256)
            g_queue[sb1 + j] = 0x80000000u | (0u << 10) | (i << 5) | j;
        int sb2 = (i <= 31 - LAG) ? p2_gstart(i + LAG) + (32 - (i + LAG))
                                  : (QTOT - 32 * (32 - i));
        for (int j = tid; j < 32; j += 256)
            g_queue[sb2 + j] = 0x80000000u | (1u << 10) | (i << 5) | j;
    }
}

// ---------------- mma / cp.async helpers ----------------
__device__ __forceinline__ void ldsm4(uint32_t* r, uint32_t addr) {
    asm volatile("ldmatrix.sync.aligned.m8n8.x4.shared.b16 {%0,%1,%2,%3}, [%4];"
                 : "=r"(r[0]), "=r"(r[1]), "=r"(r[2]), "=r"(r[3]) : "r"(addr));
}
__device__ __forceinline__ void ldsm2(uint32_t* r, uint32_t addr) {
    asm volatile("ldmatrix.sync.aligned.m8n8.x2.shared.b16 {%0,%1}, [%2];"
                 : "=r"(r[0]), "=r"(r[1]) : "r"(addr));
}
__device__ __forceinline__ void mma16816(float* d, const uint32_t* a, const uint32_t* b) {
    asm volatile(
        "mma.sync.aligned.m16n8k16.row.col.f32.bf16.bf16.f32 "
        "{%0,%1,%2,%3}, {%4,%5,%6,%7}, {%8,%9}, {%0,%1,%2,%3};"
        : "+f"(d[0]), "+f"(d[1]), "+f"(d[2]), "+f"(d[3])
        : "r"(a[0]), "r"(a[1]), "r"(a[2]), "r"(a[3]), "r"(b[0]), "r"(b[1]));
}
__device__ __forceinline__ void cpa16(uint32_t dst, const void* src) {
    asm volatile("cp.async.cg.shared.global [%0], [%1], 16;" :: "r"(dst), "l"(src));
}
#define CP_COMMIT() asm volatile("cp.async.commit_group;")
#define CP_WAIT(n)  asm volatile("cp.async.wait_group %0;" :: "n"(n))

__device__ __forceinline__ uint32_t swz(int row, int chunk) {
    return (uint32_t)(row * 256 + ((chunk ^ (row & 7)) << 4));
}

// SMEM: P=Ah (resident), Q=Bh, R=Al then Bl. 32 KB each.
#define SM_P 0
#define SM_Q 32768
#define SM_R 65536
#define SM_RS 98304
#define SM_CS 98816
#define SM_TOTAL 99328
#define TSTRIDE 136   // words; conflict-free half2 transpose scatter

// ---------------- persistent mega kernel ----------------
__global__ void __launch_bounds__(256, 2)
mega_kernel(float* __restrict__ out) {
    extern __shared__ char smem[];
    __shared__ uint32_t s_job;
    uint32_t sb = (uint32_t)__cvta_generic_to_shared(smem);
    float* rs_s = (float*)(smem + SM_RS);
    float* cs_s = (float*)(smem + SM_CS);
    int tid = threadIdx.x, wid = tid >> 5, lane = tid & 31;
    int wm = wid & 1, wn = wid >> 1;
    int g8 = lane & 7, sel = lane >> 3;
    int qr = lane >> 2, qc = (lane & 3) * 2;

    while (true) {
        if (tid == 0) {
            unsigned q = atomicAdd(&g_qhead, 1u);
            s_job = (q < QTOT) ? g_queue[q] : 0xFFFFFFFFu;
        }
        __syncthreads();
        uint32_t jd = s_job;
        if (jd == 0xFFFFFFFFu) return;

        if (jd & 0x80000000u) {
            // ================= scale chunk =================
            int p   = (jd >> 10) & 1;
            int blk = (jd >> 5) & 31;
            int sub = jd & 31;
            if (tid == 0) {
                while (atomicAdd(&g_done[p * 32 + blk], 0u) < 64u) __nanosleep(200);
            }
            __syncthreads();
            __threadfence();
            int r0 = blk * 128 + sub * 4;
            #pragma unroll
            for (int rr = 0; rr < 4; rr++) {
                int grow = r0 + rr;
                float inv = __frcp_rn(g_sums[p * NROWS + grow]);
                const uint2* src = (const uint2*)(g_stage + (size_t)grow * OCOLS + p * 8192);
                float4* dst = (float4*)out + (size_t)grow * 4096 + p * 2048;
                #pragma unroll
                for (int it = 0; it < 8; it++) {
                    int j = tid + it * 256;
                    uint2 st = src[j];
                    __half2 p0 = *reinterpret_cast<__half2*>(&st.x);
                    __half2 p1 = *reinterpret_cast<__half2*>(&st.y);
                    float2 f0 = __half22float2(p0);
                    float2 f1 = __half22float2(p1);
                    dst[j] = make_float4(f0.x * inv, f0.y * inv, f1.x * inv, f1.y * inv);
                }
            }
        } else {
            // ================= gemm job =================
            int job = (jd >> 12) & 3;            // 0=ab 1=aa 2=bb
            int ti  = (jd >> 6) & 63;
            int tj  = jd & 63;
            const __nv_bfloat16* Lh = (job == 2) ? g_bh : g_ah;
            const __nv_bfloat16* Ll = (job == 2) ? g_bl : g_al;
            const __nv_bfloat16* Rh = (job == 1) ? g_ah : g_bh;
            const __nv_bfloat16* Rl = (job == 1) ? g_al : g_bl;
            bool diag = (job != 0) && (ti == tj);
            bool doT  = (job == 0) || (ti != tj);
            int quadP = (job == 0) ? 0 : (job == 1 ? 4096 : 12288);
            int quadT = (job == 0) ? 8192 : quadP;
            int colP = quadP + tj * 128;
            int colT = quadT + ti * 128;
            int sumP = (job == 2) ? NROWS : 0;
            int sumT = (job == 1) ? 0 : NROWS;

            const __nv_bfloat16* Ah = Lh + ti * 128 * DDIM;
            const __nv_bfloat16* Al = Ll + ti * 128 * DDIM;
            const __nv_bfloat16* Bh = Rh + tj * 128 * DDIM;
            const __nv_bfloat16* Bl = Rl + tj * 128 * DDIM;

            if (tid < 128) { rs_s[tid] = 0.0f; cs_s[tid] = 0.0f; }

            #pragma unroll
            for (int it = 0; it < 8; it++) {
                int i = tid + it * 256;
                int r = i >> 4, c = i & 15;
                uint32_t so = swz(r, c);
                cpa16(sb + SM_P + so, Ah + r * DDIM + c * 8);
                cpa16(sb + SM_Q + so, Bh + r * DDIM + c * 8);
            }
            CP_COMMIT();
            #pragma unroll
            for (int it = 0; it < 8; it++) {
                int i = tid + it * 256;
                int r = i >> 4, c = i & 15;
                cpa16(sb + SM_R + swz(r, c), Al + r * DDIM + c * 8);
            }
            CP_COMMIT();

            float acc[16][4];
            #pragma unroll
            for (int i = 0; i < 16; i++)
                #pragma unroll
                for (int j = 0; j < 4; j++) acc[i][j] = 0.0f;

            auto mma_pass = [&](uint32_t abase, uint32_t bbase) {
                #pragma unroll
                for (int ks = 0; ks < 8; ks++) {
                    int kc = ks * 2;
                    uint32_t af[4][4], bf[4][2];
                    #pragma unroll
                    for (int mt = 0; mt < 4; mt++) {
                        int row = wm * 64 + mt * 16 + g8 + ((sel & 1) << 3);
                        ldsm4(af[mt], abase + swz(row, kc + (sel >> 1)));
                    }
                    #pragma unroll
                    for (int nt = 0; nt < 4; nt++) {
                        int row = wn * 32 + nt * 8 + g8;
                        ldsm2(bf[nt], bbase + swz(row, kc + (sel & 1)));
                    }
                    #pragma unroll
                    for (int mt = 0; mt < 4; mt++)
                        #pragma unroll
                        for (int nt = 0; nt < 4; nt++)
                            mma16816(acc[mt * 4 + nt], af[mt], bf[nt]);
                }
            };

            CP_WAIT(1);
            __syncthreads();
            mma_pass(sb + SM_P, sb + SM_Q);          // hh
            CP_WAIT(0);
            __syncthreads();
            mma_pass(sb + SM_R, sb + SM_Q);          // lh
            __syncthreads();
            #pragma unroll
            for (int it = 0; it < 8; it++) {
                int i = tid + it * 256;
                int r = i >> 4, c = i & 15;
                cpa16(sb + SM_R + swz(r, c), Bl + r * DDIM + c * 8);
            }
            CP_COMMIT();
            CP_WAIT(0);
            __syncthreads();
            mma_pass(sb + SM_P, sb + SM_R);          // hl
            __syncthreads();

            // exp + diag mask
            #pragma unroll
            for (int mt = 0; mt < 4; mt++)
                #pragma unroll
                for (int nt = 0; nt < 4; nt++) {
                    float* a = acc[mt * 4 + nt];
                    #pragma unroll
                    for (int j = 0; j < 4; j++) a[j] = __expf(a[j] * 10.0f);
                    if (diag) {
                        int cl = wn * 32 + nt * 8 + qc;
                        #pragma unroll
                        for (int h = 0; h < 2; h++) {
                            int rl = wm * 64 + mt * 16 + h * 8 + qr;
                            if (cl == rl)     a[h * 2 + 0] = 0.0f;
                            if (cl + 1 == rl) a[h * 2 + 1] = 0.0f;
                        }
                    }
                }

            // primary fp16 stores + row sums
            #pragma unroll
            for (int mt = 0; mt < 4; mt++) {
                #pragma unroll
                for (int h = 0; h < 2; h++) {
                    int rloc = wm * 64 + mt * 16 + h * 8 + qr;
                    int grow = ti * 128 + rloc;
                    __half* rowp = g_stage + (size_t)grow * OCOLS + colP;
                    float rsum = 0.0f;
                    #pragma unroll
                    for (int nt = 0; nt < 4; nt++) {
                        int cloc = wn * 32 + nt * 8 + qc;
                        const float* a = acc[mt * 4 + nt];
                        float v0 = a[h * 2 + 0], v1 = a[h * 2 + 1];
                        rsum += v0 + v1;
                        *(__half2*)(rowp + cloc) = __floats2half2_rn(v0, v1);
                    }
                    rsum += __shfl_xor_sync(0xffffffffu, rsum, 1);
                    rsum += __shfl_xor_sync(0xffffffffu, rsum, 2);
                    if ((lane & 3) == 0) atomicAdd(&rs_s[rloc], rsum);
                }
            }

            // column sums
            #pragma unroll
            for (int nt = 0; nt < 4; nt++) {
                float c0s = 0.0f, c1s = 0.0f;
                #pragma unroll
                for (int mt = 0; mt < 4; mt++) {
                    const float* a = acc[mt * 4 + nt];
                    c0s += a[0] + a[2];
                    c1s += a[1] + a[3];
                }
                #pragma unroll
                for (int o = 4; o <= 16; o <<= 1) {
                    c0s += __shfl_xor_sync(0xffffffffu, c0s, o);
                    c1s += __shfl_xor_sync(0xffffffffu, c1s, o);
                }
                if (lane < 4) {
                    int cloc = wn * 32 + nt * 8 + qc;
                    atomicAdd(&cs_s[cloc], c0s);
                    atomicAdd(&cs_s[cloc + 1], c1s);
                }
            }

            // transpose stage (packed half2, conflict-free)
            if (doT) {
                uint32_t* stg = (uint32_t*)smem;
                #pragma unroll
                for (int mt = 0; mt < 4; mt++)
                    #pragma unroll
                    for (int nt = 0; nt < 4; nt++) {
                        const float* a = acc[mt * 4 + nt];
                        int cp = (wn * 32 + nt * 8 + qc) >> 1;
                        #pragma unroll
                        for (int h = 0; h < 2; h++) {
                            int rloc = wm * 64 + mt * 16 + h * 8 + qr;
                            __half2 hv = __floats2half2_rn(a[h * 2 + 0], a[h * 2 + 1]);
                            stg[cp * TSTRIDE + rloc] = *reinterpret_cast<uint32_t*>(&hv);
                        }
                    }
            }
            __syncthreads();

            if (doT) {
                const uint32_t* stg = (const uint32_t*)smem;
                #pragma unroll
                for (int rr = 0; rr < 8; rr++) {
                    int cp = wid * 8 + rr;
                    uint4 q = *(const uint4*)(stg + cp * TSTRIDE + lane * 4);
                    uint32_t l0 = __byte_perm(q.x, q.y, 0x5410);
                    uint32_t l1 = __byte_perm(q.z, q.w, 0x5410);
                    uint32_t h0 = __byte_perm(q.x, q.y, 0x7632);
                    uint32_t h1 = __byte_perm(q.z, q.w, 0x7632);
                    size_t base = (size_t)(tj * 128 + 2 * cp) * OCOLS + colT + lane * 4;
                    *(uint2*)(g_stage + base)         = make_uint2(l0, l1);
                    *(uint2*)(g_stage + base + OCOLS) = make_uint2(h0, h1);
                }
            }

            if (tid < 128) {
                atomicAdd(&g_sums[sumP + ti * 128 + tid], rs_s[tid]);
                if (doT) atomicAdd(&g_sums[sumT + tj * 128 + tid], cs_s[tid]);
            }

            // release: per-thread fence, then block-uniform counter bump
            __threadfence();
            __syncthreads();
            if (tid == 0)
                atomicAdd(&g_done[((job == 2) ? 32 : 0) + ti], 1u);
            if (tid == 1 && doT)
                atomicAdd(&g_done[((job == 1) ? 0 : 32) + tj], 1u);
        }
        __syncthreads();   // protect s_job before next iteration
    }
}

extern "C" void kernel_launch(void* const* d_in, const int* in_sizes, int n_in,
                              void* d_out, int out_size) {
    const float* z1 = (const float*)d_in[0];
    const float* z2 = (const float*)d_in[1];
    float* out = (float*)d_out;

    cudaFuncSetAttribute(mega_kernel,
                         cudaFuncAttributeMaxDynamicSharedMemorySize, SM_TOTAL);

    norm_kernel<<<2 * NROWS, 128>>>(z1, z2);
    init_kernel<<<1, 256>>>();
    mega_kernel<<<296, 256, SM_TOTAL>>>(out);
}